// round 2
// baseline (speedup 1.0000x reference)
#include <cuda_runtime.h>
#include <math.h>

// Problem constants
#define NB     8
#define TT     64
#define JJ     25
#define CC     256       // D_MODEL
#define DI     512       // D_INNER
#define DS     16        // D_STATE
#define DTR    16        // DT_RANK
#define BTOT   (NB*JJ)   // 200
#define NROWS  (BTOT*TT) // 12800

// ---------------- scratch (__device__ globals; no allocation) ----------------
__device__ float g_WT_in [CC * (2*DI)];     // [c][e]  1 MB
__device__ float g_WT_out[DI * CC];         // [d][c]  0.5 MB
__device__ float g_xc [NROWS * DI];         // pre-conv x branch
__device__ float g_xc2[NROWS * DI];         // post conv+silu
__device__ float g_z  [NROWS * DI];
__device__ float g_dt [NROWS * DI];
__device__ float g_y  [NROWS * DI];
__device__ float g_Bm [NROWS * DS];
__device__ float g_Cm [NROWS * DS];

// ---------------- helpers ----------------
__device__ __forceinline__ float silu_f(float v) {
    return v / (1.0f + __expf(-v));
}
__device__ __forceinline__ float softplus_f(float v) {
    // stable: max(v,0) + log1p(exp(-|v|))
    return fmaxf(v, 0.0f) + log1pf(__expf(-fabsf(v)));
}

// ---------------- k0: weight transposes ----------------
__global__ void k0_transpose(const float* __restrict__ W, float* __restrict__ WT,
                             int R, int C) {
    int idx = blockIdx.x * blockDim.x + threadIdx.x;
    if (idx < R * C) {
        int r = idx / C, c = idx - r * C;
        WT[c * R + r] = W[r * C + c];
    }
}

// ---------------- k1: in-projection GEMM ----------------
// xz[m, e] = sum_c xr[m, c] * W_in[e, c],  m = b*64+t, b = n*25+j
// 16 rows x 1024 cols per block, 256 threads, 4 cols/thread, 64 fp32 accs.
__global__ __launch_bounds__(256) void k1_gemm_in(const float* __restrict__ x) {
    __shared__ __align__(16) float sx[16][CC];
    const int tid = threadIdx.x;
    const int m0  = blockIdx.x * 16;

    #pragma unroll
    for (int r = 0; r < 16; r++) {
        int m = m0 + r;
        int b = m >> 6, t = m & 63;
        int n = b / 25, j = b - n * 25;
        sx[r][tid] = x[((n * TT + t) * JJ + j) * CC + tid];
    }
    __syncthreads();

    float acc[16][4];
    #pragma unroll
    for (int r = 0; r < 16; r++)
        #pragma unroll
        for (int q = 0; q < 4; q++) acc[r][q] = 0.0f;

    for (int c = 0; c < CC; c++) {
        const float* wp = &g_WT_in[c * (2*DI)];
        float w0 = wp[tid];
        float w1 = wp[tid + 256];
        float w2 = wp[tid + 512];
        float w3 = wp[tid + 768];
        #pragma unroll
        for (int r = 0; r < 16; r++) {
            float xv = sx[r][c];
            acc[r][0] = fmaf(xv, w0, acc[r][0]);
            acc[r][1] = fmaf(xv, w1, acc[r][1]);
            acc[r][2] = fmaf(xv, w2, acc[r][2]);
            acc[r][3] = fmaf(xv, w3, acc[r][3]);
        }
    }

    #pragma unroll
    for (int r = 0; r < 16; r++) {
        int m = m0 + r;
        g_xc[m * DI + tid]        = acc[r][0];   // e = tid        (< 512)
        g_xc[m * DI + tid + 256]  = acc[r][1];   // e = tid+256    (< 512)
        g_z [m * DI + tid]        = acc[r][2];   // e = tid+512 -> z[tid]
        g_z [m * DI + tid + 256]  = acc[r][3];   // e = tid+768 -> z[tid+256]
    }
}

// ---------------- k2: depthwise causal conv + bias + SiLU ----------------
__global__ void k2_conv(const float* __restrict__ conv_w,
                        const float* __restrict__ conv_b) {
    int idx = blockIdx.x * blockDim.x + threadIdx.x;
    if (idx >= NROWS * DI) return;
    int d = idx & (DI - 1);
    int m = idx >> 9;        // b*64 + t
    int t = m & 63;
    float s = conv_b[d];
    #pragma unroll
    for (int k = 0; k < 4; k++) {
        int tt = t - 3 + k;
        if (tt >= 0) s = fmaf(conv_w[d * 4 + k], g_xc[(m - 3 + k) * DI + d], s);
    }
    g_xc2[idx] = silu_f(s);
}

// ---------------- k3: x_dbl projection + dt projection + softplus ----------------
// warp per row m: x_dbl[e] = sum_d xc2[d]*W_xproj[e,d]  (48 outs, K=512)
// then dt[d] = softplus(sum_r x_dbl[r]*W_dt[d,r] + b_dt[d])  (512 outs, K=16)
__global__ __launch_bounds__(256) void k3_xproj(const float* __restrict__ Wx,
                                                const float* __restrict__ Wdt,
                                                const float* __restrict__ bdt) {
    __shared__ float sdbl[8][48];
    const int lane = threadIdx.x & 31;
    const int w    = threadIdx.x >> 5;
    const int m    = blockIdx.x * 8 + w;

    float xrow[16];
    #pragma unroll
    for (int i = 0; i < 16; i++) xrow[i] = g_xc2[m * DI + lane + 32 * i];

    for (int e = 0; e < 48; e++) {
        float p = 0.0f;
        const float* wr = &Wx[e * DI + lane];
        #pragma unroll
        for (int i = 0; i < 16; i++) p = fmaf(xrow[i], __ldg(&wr[32 * i]), p);
        #pragma unroll
        for (int off = 16; off; off >>= 1) p += __shfl_xor_sync(0xffffffffu, p, off);
        if (lane == 0) sdbl[w][e] = p;
    }
    __syncwarp();

    if (lane < 16) g_Bm[m * DS + lane]        = sdbl[w][DTR + lane];
    else           g_Cm[m * DS + (lane - 16)] = sdbl[w][DTR + lane]; // 32..47

    #pragma unroll
    for (int i = 0; i < 16; i++) {
        int d = lane + 32 * i;
        float a = bdt[d];
        #pragma unroll
        for (int r = 0; r < DTR; r++) a = fmaf(sdbl[w][r], __ldg(&Wdt[d * DTR + r]), a);
        g_dt[m * DI + d] = softplus_f(a);
    }
}

// ---------------- k4: selective scan + skip + gating ----------------
// Block per sequence b. Thread owns 2 channels x 16 states in registers.
__global__ __launch_bounds__(256) void k4_scan(const float* __restrict__ A_log,
                                               const float* __restrict__ D_skip) {
    __shared__ float sB[DS], sC[DS];
    const int tid = threadIdx.x;
    const int b   = blockIdx.x;
    const int d0  = tid * 2;

    float Aa[2][DS], h[2][DS];
    #pragma unroll
    for (int j = 0; j < 2; j++)
        #pragma unroll
        for (int s = 0; s < DS; s++) {
            Aa[j][s] = -__expf(A_log[(d0 + j) * DS + s]);
            h[j][s]  = 0.0f;
        }
    float Dk[2] = { D_skip[d0], D_skip[d0 + 1] };

    for (int t = 0; t < TT; t++) {
        int base = b * TT + t;
        if (tid < DS)           sB[tid]      = g_Bm[base * DS + tid];
        else if (tid < 2 * DS)  sC[tid - DS] = g_Cm[base * DS + (tid - DS)];
        __syncthreads();

        float2 dtv = *(const float2*)&g_dt [base * DI + d0];
        float2 xcv = *(const float2*)&g_xc2[base * DI + d0];
        float2 zv  = *(const float2*)&g_z  [base * DI + d0];
        float dts[2] = { dtv.x, dtv.y };
        float xcs[2] = { xcv.x, xcv.y };
        float zs [2] = { zv.x,  zv.y  };
        float yv[2];

        #pragma unroll
        for (int j = 0; j < 2; j++) {
            float du = dts[j] * xcs[j];
            float y  = 0.0f;
            #pragma unroll
            for (int s = 0; s < DS; s++) {
                float dA = __expf(dts[j] * Aa[j][s]);
                h[j][s]  = fmaf(dA, h[j][s], du * sB[s]);
                y        = fmaf(h[j][s], sC[s], y);
            }
            y = fmaf(xcs[j], Dk[j], y);
            yv[j] = y * silu_f(zs[j]);
        }
        *(float2*)&g_y[base * DI + d0] = make_float2(yv[0], yv[1]);
        __syncthreads();
    }
}

// ---------------- k5: out-projection GEMM + RMSNorm + residual + transpose ----------------
// out[m, c] = sum_d y[m,d]*W_out[c,d]; rmsnorm over c; + x residual.
__global__ __launch_bounds__(256) void k5_gemm_out(const float* __restrict__ x,
                                                   const float* __restrict__ ln_w,
                                                   float* __restrict__ out) {
    __shared__ __align__(16) float sy[16][DI];
    __shared__ float part[16][8];
    __shared__ float srms[16];
    const int tid = threadIdx.x;
    const int m0  = blockIdx.x * 16;

    #pragma unroll
    for (int r = 0; r < 16; r++) {
        int m = m0 + r;
        sy[r][tid]       = g_y[m * DI + tid];
        sy[r][tid + 256] = g_y[m * DI + tid + 256];
    }
    __syncthreads();

    float acc[16];
    #pragma unroll
    for (int r = 0; r < 16; r++) acc[r] = 0.0f;

    for (int d = 0; d < DI; d += 4) {
        float w0 = g_WT_out[(d    ) * CC + tid];
        float w1 = g_WT_out[(d + 1) * CC + tid];
        float w2 = g_WT_out[(d + 2) * CC + tid];
        float w3 = g_WT_out[(d + 3) * CC + tid];
        #pragma unroll
        for (int r = 0; r < 16; r++) {
            float4 v = *(const float4*)&sy[r][d];
            acc[r] = fmaf(w0, v.x, acc[r]);
            acc[r] = fmaf(w1, v.y, acc[r]);
            acc[r] = fmaf(w2, v.z, acc[r]);
            acc[r] = fmaf(w3, v.w, acc[r]);
        }
    }

    const int lane = tid & 31, wid = tid >> 5;
    #pragma unroll
    for (int r = 0; r < 16; r++) {
        float v = acc[r] * acc[r];
        #pragma unroll
        for (int off = 16; off; off >>= 1) v += __shfl_xor_sync(0xffffffffu, v, off);
        if (lane == 0) part[r][wid] = v;
    }
    __syncthreads();
    if (tid < 16) {
        float s = 0.0f;
        #pragma unroll
        for (int q = 0; q < 8; q++) s += part[tid][q];
        srms[tid] = rsqrtf(s * (1.0f / CC) + 1e-6f);
    }
    __syncthreads();

    float lw = ln_w[tid];
    #pragma unroll
    for (int r = 0; r < 16; r++) {
        int m = m0 + r;
        int b = m >> 6, t = m & 63;
        int n = b / 25, j = b - n * 25;
        int idx = ((n * TT + t) * JJ + j) * CC + tid;
        out[idx] = fmaf(acc[r] * srms[r], lw, x[idx]);
    }
}

// ---------------- launch ----------------
extern "C" void kernel_launch(void* const* d_in, const int* in_sizes, int n_in,
                              void* d_out, int out_size) {
    const float* x      = (const float*)d_in[0];
    const float* W_in   = (const float*)d_in[1];
    const float* conv_w = (const float*)d_in[2];
    const float* conv_b = (const float*)d_in[3];
    const float* W_xprj = (const float*)d_in[4];
    const float* W_dt   = (const float*)d_in[5];
    const float* b_dt   = (const float*)d_in[6];
    const float* A_log  = (const float*)d_in[7];
    const float* D_skip = (const float*)d_in[8];
    const float* W_out  = (const float*)d_in[9];
    const float* ln_w   = (const float*)d_in[10];
    float* out = (float*)d_out;

    float* wt_in;  cudaGetSymbolAddress((void**)&wt_in,  g_WT_in);
    float* wt_out; cudaGetSymbolAddress((void**)&wt_out, g_WT_out);

    k0_transpose<<<(2*DI*CC + 255) / 256, 256>>>(W_in,  wt_in,  2*DI, CC);
    k0_transpose<<<(CC*DI  + 255) / 256, 256>>>(W_out, wt_out, CC,  DI);

    k1_gemm_in<<<NROWS / 16, 256>>>(x);
    k2_conv<<<(NROWS * DI) / 256, 256>>>(conv_w, conv_b);
    k3_xproj<<<NROWS / 8, 256>>>(W_xprj, W_dt, b_dt);
    k4_scan<<<BTOT, 256>>>(A_log, D_skip);
    k5_gemm_out<<<NROWS / 16, 256>>>(x, ln_w, out);
}

// round 3
// speedup vs baseline: 2.0918x; 2.0918x over previous
#include <cuda_runtime.h>
#include <math.h>
#include <stdint.h>

// Problem constants
#define NB     8
#define TT     64
#define JJ     25
#define CC     256       // D_MODEL
#define DI     512       // D_INNER
#define DS     16        // D_STATE
#define DTR    16        // DT_RANK
#define BTOT   (NB*JJ)   // 200
#define NROWS  (BTOT*TT) // 12800

// ---------------- scratch ----------------
__device__ float g_xc [NROWS * DI];
__device__ float g_xc2[NROWS * DI];
__device__ float g_z  [NROWS * DI];
__device__ float g_dt [NROWS * DI];
__device__ float g_y  [NROWS * DI];
__device__ float g_Bm [NROWS * DS];
__device__ float g_Cm [NROWS * DS];

// ---------------- helpers ----------------
__device__ __forceinline__ float silu_f(float v) { return v / (1.0f + __expf(-v)); }
__device__ __forceinline__ float softplus_f(float v) {
    return fmaxf(v, 0.0f) + log1pf(__expf(-fabsf(v)));
}
__device__ __forceinline__ uint32_t f2t(float f) {
    uint32_t u; asm("cvt.rna.tf32.f32 %0, %1;" : "=r"(u) : "f"(f)); return u;
}
__device__ __forceinline__ void mma8(float* c, uint32_t a0, uint32_t a1, uint32_t a2,
                                     uint32_t a3, uint32_t b0, uint32_t b1) {
    asm volatile(
        "mma.sync.aligned.m16n8k8.row.col.f32.tf32.tf32.f32 "
        "{%0,%1,%2,%3},{%4,%5,%6,%7},{%8,%9},{%0,%1,%2,%3};"
        : "+f"(c[0]), "+f"(c[1]), "+f"(c[2]), "+f"(c[3])
        : "r"(a0), "r"(a1), "r"(a2), "r"(a3), "r"(b0), "r"(b1));
}

// ---------------- k1: in-projection GEMM (tf32 mma) ----------------
// xz[m,e] = sum_c xr[m,c] * W_in[e,c].  Block: 64 rows (one sequence) x 128 cols.
__global__ __launch_bounds__(256) void k1_gemm_in(const float* __restrict__ x,
                                                  const float* __restrict__ W) {
    __shared__ uint32_t sA[64][36];
    __shared__ uint32_t sB[128][36];
    const int tid = threadIdx.x, lane = tid & 31, warp = tid >> 5;
    const int lr = lane >> 2, lk = lane & 3;
    const int b = blockIdx.x, n0 = blockIdx.y * 128;
    const int n = b / 25, j = b - n * 25;
    const float* xbase = x + ((size_t)(n * TT) * JJ + j) * CC;  // row t: + t*JJ*CC
    const int wr = (warp >> 2) * 32, wc = (warp & 3) * 32;

    float acc[2][4][4];
    #pragma unroll
    for (int i = 0; i < 2; i++)
        #pragma unroll
        for (int jj = 0; jj < 4; jj++)
            #pragma unroll
            for (int q = 0; q < 4; q++) acc[i][jj][q] = 0.0f;

    const int ar = tid >> 2, ac = (tid & 3) * 8;   // A: 64 rows x 32, 2 float4/thread
    const int br = tid >> 1, bc = (tid & 1) * 16;  // B: 128 rows x 32, 4 float4/thread

    for (int c0 = 0; c0 < CC; c0 += 32) {
        __syncthreads();
        {
            const float4* p = (const float4*)(xbase + (size_t)ar * JJ * CC + c0 + ac);
            float4 v0 = p[0], v1 = p[1];
            sA[ar][ac+0]=f2t(v0.x); sA[ar][ac+1]=f2t(v0.y); sA[ar][ac+2]=f2t(v0.z); sA[ar][ac+3]=f2t(v0.w);
            sA[ar][ac+4]=f2t(v1.x); sA[ar][ac+5]=f2t(v1.y); sA[ar][ac+6]=f2t(v1.z); sA[ar][ac+7]=f2t(v1.w);
        }
        {
            const float4* p = (const float4*)(W + (size_t)(n0 + br) * CC + c0 + bc);
            #pragma unroll
            for (int q = 0; q < 4; q++) {
                float4 v = p[q];
                sB[br][bc+4*q+0]=f2t(v.x); sB[br][bc+4*q+1]=f2t(v.y);
                sB[br][bc+4*q+2]=f2t(v.z); sB[br][bc+4*q+3]=f2t(v.w);
            }
        }
        __syncthreads();
        #pragma unroll
        for (int kk = 0; kk < 4; kk++) {
            const int k0 = kk * 8;
            uint32_t a[2][4], bb[4][2];
            #pragma unroll
            for (int i = 0; i < 2; i++) {
                a[i][0] = sA[wr+16*i+lr  ][k0+lk];
                a[i][1] = sA[wr+16*i+8+lr][k0+lk];
                a[i][2] = sA[wr+16*i+lr  ][k0+lk+4];
                a[i][3] = sA[wr+16*i+8+lr][k0+lk+4];
            }
            #pragma unroll
            for (int jj = 0; jj < 4; jj++) {
                bb[jj][0] = sB[wc+8*jj+lr][k0+lk];
                bb[jj][1] = sB[wc+8*jj+lr][k0+lk+4];
            }
            #pragma unroll
            for (int i = 0; i < 2; i++)
                #pragma unroll
                for (int jj = 0; jj < 4; jj++)
                    mma8(acc[i][jj], a[i][0], a[i][1], a[i][2], a[i][3], bb[jj][0], bb[jj][1]);
        }
    }

    float* dst; int eoff;
    if (n0 < DI) { dst = g_xc; eoff = n0; } else { dst = g_z; eoff = n0 - DI; }
    #pragma unroll
    for (int i = 0; i < 2; i++) {
        const int r0 = wr + 16*i + lr, r1 = r0 + 8;
        const size_t m0r = (size_t)(b * TT + r0) * DI;
        const size_t m1r = (size_t)(b * TT + r1) * DI;
        #pragma unroll
        for (int jj = 0; jj < 4; jj++) {
            const int col = eoff + wc + 8*jj + 2*lk;
            *(float2*)&dst[m0r + col] = make_float2(acc[i][jj][0], acc[i][jj][1]);
            *(float2*)&dst[m1r + col] = make_float2(acc[i][jj][2], acc[i][jj][3]);
        }
    }
}

// ---------------- k2: depthwise causal conv + bias + SiLU ----------------
__global__ void k2_conv(const float* __restrict__ conv_w,
                        const float* __restrict__ conv_b) {
    int idx = blockIdx.x * blockDim.x + threadIdx.x;
    if (idx >= NROWS * DI) return;
    int d = idx & (DI - 1);
    int m = idx >> 9;
    int t = m & 63;
    float s = conv_b[d];
    #pragma unroll
    for (int k = 0; k < 4; k++) {
        int tt = t - 3 + k;
        if (tt >= 0) s = fmaf(conv_w[d * 4 + k], g_xc[(size_t)(m - 3 + k) * DI + d], s);
    }
    g_xc2[idx] = silu_f(s);
}

// ---------------- k3: x_dbl projection + dt projection (tiled, shared weights) --------
// Block = 64 rows. Phase 1: x_dbl[64x48] = xc2[64x512] @ Wx^T (smem tiles).
// Phase 2: dt[64x512] from x_dbl[:, :16] @ Wdt^T (+softplus); Bm/Cm split.
__global__ __launch_bounds__(256) void k3_xproj(const float* __restrict__ Wx,
                                                const float* __restrict__ Wdt,
                                                const float* __restrict__ bdt) {
    __shared__ float buf[12032];          // 47 KB, phase-overlaid
    float* sX = buf;                      // [64][65]
    float* sW = buf + 64 * 65;            // [48][65]
    const int tid = threadIdx.x;
    const int m0 = blockIdx.x * 64;
    const int row = tid >> 2, c0 = (tid & 3) * 12;

    float acc[12];
    #pragma unroll
    for (int i = 0; i < 12; i++) acc[i] = 0.0f;

    for (int k0 = 0; k0 < DI; k0 += 64) {
        __syncthreads();
        for (int idx = tid; idx < 64 * 64; idx += 256) {
            int r = idx >> 6, k = idx & 63;
            sX[r * 65 + k] = g_xc2[(size_t)(m0 + r) * DI + k0 + k];
        }
        for (int idx = tid; idx < 48 * 64; idx += 256) {
            int r = idx >> 6, k = idx & 63;
            sW[r * 65 + k] = Wx[(size_t)r * DI + k0 + k];
        }
        __syncthreads();
        for (int k = 0; k < 64; k++) {
            float a = sX[row * 65 + k];
            #pragma unroll
            for (int i = 0; i < 12; i++) acc[i] = fmaf(a, sW[(c0 + i) * 65 + k], acc[i]);
        }
    }
    __syncthreads();

    float* sD   = buf;                    // [64][52]
    float* sWdt = buf + 64 * 52;          // [512][17]
    #pragma unroll
    for (int i = 0; i < 12; i++) sD[row * 52 + c0 + i] = acc[i];
    for (int idx = tid; idx < DI * DTR; idx += 256) {
        int d = idx >> 4, r = idx & 15;
        sWdt[d * 17 + r] = Wdt[idx];
    }
    __syncthreads();

    for (int idx = tid; idx < 64 * 32; idx += 256) {
        int r = idx >> 5, v = idx & 31;
        float val = sD[r * 52 + DTR + v];
        if (v < 16) g_Bm[(size_t)(m0 + r) * DS + v]        = val;
        else        g_Cm[(size_t)(m0 + r) * DS + (v - 16)] = val;
    }
    for (int idx = tid; idx < 64 * DI; idx += 256) {
        int r = idx >> 9, d = idx & 511;
        float a = bdt[d];
        #pragma unroll
        for (int q = 0; q < 16; q++) a = fmaf(sD[r * 52 + q], sWdt[d * 17 + q], a);
        g_dt[(size_t)(m0 + r) * DI + d] = softplus_f(a);
    }
}

// ---------------- k4: selective scan + skip + gating ----------------
// grid (200, 2): each thread owns one channel, 16 states in registers.
__global__ __launch_bounds__(256) void k4_scan(const float* __restrict__ A_log,
                                               const float* __restrict__ D_skip) {
    __shared__ float sB[DS], sC[DS];
    const int tid = threadIdx.x;
    const int b   = blockIdx.x;
    const int d   = blockIdx.y * 256 + tid;

    float Aa[DS], h[DS];
    #pragma unroll
    for (int s = 0; s < DS; s++) {
        Aa[s] = -__expf(A_log[d * DS + s]);
        h[s]  = 0.0f;
    }
    float Dk = D_skip[d];

    for (int t = 0; t < TT; t++) {
        int base = b * TT + t;
        if (tid < DS)           sB[tid]      = g_Bm[base * DS + tid];
        else if (tid < 2 * DS)  sC[tid - DS] = g_Cm[base * DS + (tid - DS)];
        __syncthreads();

        float dt = g_dt [(size_t)base * DI + d];
        float xc = g_xc2[(size_t)base * DI + d];
        float z  = g_z  [(size_t)base * DI + d];
        float du = dt * xc, y = 0.0f;
        #pragma unroll
        for (int s = 0; s < DS; s++) {
            float dA = __expf(dt * Aa[s]);
            h[s] = fmaf(dA, h[s], du * sB[s]);
            y    = fmaf(h[s], sC[s], y);
        }
        y = fmaf(xc, Dk, y);
        g_y[(size_t)base * DI + d] = y * silu_f(z);
        __syncthreads();
    }
}

// ---------------- k5: out-projection GEMM (tf32 mma) + RMSNorm + residual ----------
// Block: 32 rows x 256 cols (full N so RMSNorm is block-local). grid 400.
__global__ __launch_bounds__(256) void k5_gemm_out(const float* __restrict__ x,
                                                   const float* __restrict__ W,
                                                   const float* __restrict__ ln_w,
                                                   float* __restrict__ out) {
    __shared__ uint32_t sA[32][36];
    __shared__ uint32_t sB[256][36];
    __shared__ float rowsq[32];
    const int tid = threadIdx.x, lane = tid & 31, warp = tid >> 5;
    const int lr = lane >> 2, lk = lane & 3;
    const int m0 = blockIdx.x * 32;
    const int wr = (warp >> 2) * 16, wc = (warp & 3) * 64;

    if (tid < 32) rowsq[tid] = 0.0f;

    float acc[8][4];
    #pragma unroll
    for (int jj = 0; jj < 8; jj++)
        #pragma unroll
        for (int q = 0; q < 4; q++) acc[jj][q] = 0.0f;

    const int ar = tid >> 3, ac = (tid & 7) * 4;   // A: 32x32, 1 float4/thread
    const int br = tid;                            // B: 256x32, 8 float4/thread

    for (int d0 = 0; d0 < DI; d0 += 32) {
        __syncthreads();
        {
            float4 v = *(const float4*)&g_y[(size_t)(m0 + ar) * DI + d0 + ac];
            sA[ar][ac]=f2t(v.x); sA[ar][ac+1]=f2t(v.y); sA[ar][ac+2]=f2t(v.z); sA[ar][ac+3]=f2t(v.w);
        }
        {
            const float4* p = (const float4*)(W + (size_t)br * DI + d0);
            #pragma unroll
            for (int q = 0; q < 8; q++) {
                float4 v = p[q];
                sB[br][4*q]=f2t(v.x); sB[br][4*q+1]=f2t(v.y); sB[br][4*q+2]=f2t(v.z); sB[br][4*q+3]=f2t(v.w);
            }
        }
        __syncthreads();
        #pragma unroll
        for (int kk = 0; kk < 4; kk++) {
            const int k0 = kk * 8;
            uint32_t a0 = sA[wr+lr][k0+lk],   a1 = sA[wr+8+lr][k0+lk];
            uint32_t a2 = sA[wr+lr][k0+lk+4], a3 = sA[wr+8+lr][k0+lk+4];
            #pragma unroll
            for (int jj = 0; jj < 8; jj++) {
                uint32_t b0 = sB[wc+8*jj+lr][k0+lk];
                uint32_t b1 = sB[wc+8*jj+lr][k0+lk+4];
                mma8(acc[jj], a0, a1, a2, a3, b0, b1);
            }
        }
    }

    // per-row sum of squares (4 col-warps share rows)
    float s0 = 0.0f, s1 = 0.0f;
    #pragma unroll
    for (int jj = 0; jj < 8; jj++) {
        s0 += acc[jj][0]*acc[jj][0] + acc[jj][1]*acc[jj][1];
        s1 += acc[jj][2]*acc[jj][2] + acc[jj][3]*acc[jj][3];
    }
    s0 += __shfl_xor_sync(0xffffffffu, s0, 1); s0 += __shfl_xor_sync(0xffffffffu, s0, 2);
    s1 += __shfl_xor_sync(0xffffffffu, s1, 1); s1 += __shfl_xor_sync(0xffffffffu, s1, 2);
    if (lk == 0) { atomicAdd(&rowsq[wr + lr], s0); atomicAdd(&rowsq[wr + 8 + lr], s1); }
    __syncthreads();

    const int r0 = wr + lr, r1 = wr + 8 + lr;
    float rms0 = rsqrtf(rowsq[r0] * (1.0f / CC) + 1e-6f);
    float rms1 = rsqrtf(rowsq[r1] * (1.0f / CC) + 1e-6f);

    const int m0r = m0 + r0, m1r = m0 + r1;
    const int t0 = m0r & 63, b0_ = m0r >> 6, n_0 = b0_ / 25, j0 = b0_ - n_0 * 25;
    const int t1 = m1r & 63, b1_ = m1r >> 6, n_1 = b1_ / 25, j1 = b1_ - n_1 * 25;
    const size_t g0 = ((size_t)(n_0 * TT + t0) * JJ + j0) * CC;
    const size_t g1 = ((size_t)(n_1 * TT + t1) * JJ + j1) * CC;
    #pragma unroll
    for (int jj = 0; jj < 8; jj++) {
        const int col = wc + 8*jj + 2*lk;
        float2 lw = *(const float2*)&ln_w[col];
        float2 x0 = *(const float2*)&x[g0 + col];
        float2 x1 = *(const float2*)&x[g1 + col];
        *(float2*)&out[g0 + col] = make_float2(fmaf(acc[jj][0]*rms0, lw.x, x0.x),
                                               fmaf(acc[jj][1]*rms0, lw.y, x0.y));
        *(float2*)&out[g1 + col] = make_float2(fmaf(acc[jj][2]*rms1, lw.x, x1.x),
                                               fmaf(acc[jj][3]*rms1, lw.y, x1.y));
    }
}

// ---------------- launch ----------------
extern "C" void kernel_launch(void* const* d_in, const int* in_sizes, int n_in,
                              void* d_out, int out_size) {
    const float* x      = (const float*)d_in[0];
    const float* W_in   = (const float*)d_in[1];
    const float* conv_w = (const float*)d_in[2];
    const float* conv_b = (const float*)d_in[3];
    const float* W_xprj = (const float*)d_in[4];
    const float* W_dt   = (const float*)d_in[5];
    const float* b_dt   = (const float*)d_in[6];
    const float* A_log  = (const float*)d_in[7];
    const float* D_skip = (const float*)d_in[8];
    const float* W_out  = (const float*)d_in[9];
    const float* ln_w   = (const float*)d_in[10];
    float* out = (float*)d_out;

    k1_gemm_in<<<dim3(BTOT, 8), 256>>>(x, W_in);
    k2_conv<<<(NROWS * DI) / 256, 256>>>(conv_w, conv_b);
    k3_xproj<<<BTOT, 256>>>(W_xprj, W_dt, b_dt);
    k4_scan<<<dim3(BTOT, 2), 256>>>(A_log, D_skip);
    k5_gemm_out<<<NROWS / 32, 256>>>(x, W_out, ln_w, out);
}